// round 6
// baseline (speedup 1.0000x reference)
#include <cuda_runtime.h>
#include <cstdint>

#define TSTEPS 256
#define HSZ 50
#define ISZ 7
#define EPB 32
#define NTHREADS 512
#define NBLOCKS 128

typedef unsigned long long u64;

// smem layout (float offsets)
#define OFF_WX0 0        // [7][50][4gates]   1400
#define OFF_WH0 1400     // [50][50][4]      10000
#define OFF_WI1 11400    // [50][50][4]      10000
#define OFF_WH1 21400    // [50][50][4]      10000
#define OFF_B0  31400    // [50][4]            200
#define OFF_B1  31600    // [50][4]            200
#define OFF_WFC 31800    // [7][50]            350
#define OFF_BFC 32152    // [8]                  8
#define OFF_XA  32160    // [2][7][32] dup     448
#define OFF_XB  32608    // [2][7][32] dup     448
#define OFF_H0A 33056    // [2][50][32] dup   3200
#define OFF_H0B 36256    // [2][50][32] dup   3200
#define OFF_H1A 39456    // [2][50][32] dup   3200
#define OFF_H1B 42656    // [2][50][32] dup   3200
#define SMEM_FLOATS 45856   // 183424 bytes

__device__ __forceinline__ u64 pk2(float lo, float hi) {
    u64 r; asm("mov.b64 %0,{%1,%2};" : "=l"(r) : "f"(lo), "f"(hi)); return r;
}
__device__ __forceinline__ void upk2(float& lo, float& hi, u64 v) {
    asm("mov.b64 {%0,%1},%2;" : "=f"(lo), "=f"(hi) : "l"(v));
}
__device__ __forceinline__ void fma2(u64& c, u64 a, u64 b) {
    asm("fma.rn.f32x2 %0,%1,%2,%0;" : "+l"(c) : "l"(a), "l"(b));
}

__device__ __forceinline__ float sigm(float v) {
    return __fdividef(1.f, 1.f + __expf(-v));
}
__device__ __forceinline__ float tanh_f(float v) {
    return __fdividef(2.f, 1.f + __expf(-2.f * v)) - 1.f;
}

// matvec accumulate over N k-steps.
// Wp: [k][j][4] gate-packed weights -> (wi,wf),(wg,wo) natural u64 pairs.
// A/B: duplicated operand arrays, row stride 32 floats; thread reads 16B at g4.
// aif[e] accumulates (i,f) sums for element e; ago[e] accumulates (g,o).
template<int N>
__device__ __forceinline__ void mvN(const float* __restrict__ Wp,
                                    const float* __restrict__ A,
                                    const float* __restrict__ B,
                                    int j, int g4,
                                    u64 aif[4], u64 ago[4]) {
    #pragma unroll 10
    for (int k = 0; k < N; k++) {
        const ulonglong2 wv = *reinterpret_cast<const ulonglong2*>(Wp + (k * HSZ + j) * 4);
        const ulonglong2 da = *reinterpret_cast<const ulonglong2*>(A + k * EPB + g4);
        const ulonglong2 db = *reinterpret_cast<const ulonglong2*>(B + k * EPB + g4);
        fma2(aif[0], wv.x, da.x); fma2(aif[1], wv.x, da.y);
        fma2(aif[2], wv.x, db.x); fma2(aif[3], wv.x, db.y);
        fma2(ago[0], wv.y, da.x); fma2(ago[1], wv.y, da.y);
        fma2(ago[2], wv.y, db.x); fma2(ago[3], wv.y, db.y);
    }
}

__device__ __forceinline__ void gates4(const u64 aif[4], const u64 ago[4],
                                       float c[4], float hn[4]) {
    #pragma unroll
    for (int e = 0; e < 4; e++) {
        float iv, fv, gv, ov;
        upk2(iv, fv, aif[e]);
        upk2(gv, ov, ago[e]);
        c[e] = sigm(fv) * c[e] + sigm(iv) * tanh_f(gv);
        hn[e] = sigm(ov) * tanh_f(c[e]);
    }
}

__global__ __launch_bounds__(NTHREADS, 1)
void lstm2_fused_v3(const float* __restrict__ x,
                    const float* __restrict__ w_ih0, const float* __restrict__ w_hh0,
                    const float* __restrict__ b_ih0, const float* __restrict__ b_hh0,
                    const float* __restrict__ w_ih1, const float* __restrict__ w_hh1,
                    const float* __restrict__ b_ih1, const float* __restrict__ b_hh1,
                    const float* __restrict__ w_fc,  const float* __restrict__ b_fc,
                    float* __restrict__ out)
{
    extern __shared__ float sm[];
    const int tid = threadIdx.x;
    const int blk = blockIdx.x;

    // ---- stage weights, gate-interleaved [k][j][i,f,g,o] ----
    for (int i = tid; i < HSZ * HSZ * 4; i += NTHREADS) {
        const int gi = i & 3, j = (i >> 2) % HSZ, k = i / 200;
        const int src = (gi * HSZ + j) * HSZ + k;
        sm[OFF_WH0 + i] = w_hh0[src];
        sm[OFF_WI1 + i] = w_ih1[src];
        sm[OFF_WH1 + i] = w_hh1[src];
    }
    for (int i = tid; i < ISZ * HSZ * 4; i += NTHREADS) {
        const int gi = i & 3, j = (i >> 2) % HSZ, k = i / 200;
        sm[OFF_WX0 + i] = w_ih0[(gi * HSZ + j) * ISZ + k];
    }
    for (int i = tid; i < 200; i += NTHREADS) {
        const int gi = i & 3, j = i >> 2;
        sm[OFF_B0 + i] = b_ih0[gi * HSZ + j] + b_hh0[gi * HSZ + j];
        sm[OFF_B1 + i] = b_ih1[gi * HSZ + j] + b_hh1[gi * HSZ + j];
    }
    for (int i = tid; i < ISZ * HSZ; i += NTHREADS) sm[OFF_WFC + i] = w_fc[i];
    if (tid < ISZ) sm[OFF_BFC + tid] = b_fc[tid];
    // zero all h dup buffers (both phases)
    for (int i = tid; i < 2 * HSZ * EPB; i += NTHREADS) {
        sm[OFF_H0A + i] = 0.f; sm[OFF_H0B + i] = 0.f;
        sm[OFF_H1A + i] = 0.f; sm[OFF_H1B + i] = 0.f;
    }
    // preload x(t=0) duplicated into buf 0
    if (tid < EPB * ISZ) {
        const int e = tid & 31, kx = tid >> 5;
        const float xv = x[(size_t)(blk * EPB + e) * (TSTEPS * ISZ) + kx];
        const int gg = e >> 2, r = e & 3;
        float* dst = sm + (r < 2 ? OFF_XA : OFF_XB) + kx * EPB + gg * 4 + (r & 1) * 2;
        *reinterpret_cast<u64*>(dst) = pk2(xv, xv);
    }
    __syncthreads();

    const int j  = tid >> 3;         // cell slot 0..63 (active < 50)
    const int g  = tid & 7;          // element group: elements 4g..4g+3
    const int g4 = g * 4;            // float offset in dup row
    const bool act = (j < HSZ);

    u64 bif0 = 0, bgo0 = 0, bif1 = 0, bgo1 = 0;
    if (act) {
        const ulonglong2 bb0 = *reinterpret_cast<const ulonglong2*>(sm + OFF_B0 + j * 4);
        const ulonglong2 bb1 = *reinterpret_cast<const ulonglong2*>(sm + OFF_B1 + j * 4);
        bif0 = bb0.x; bgo0 = bb0.y;
        bif1 = bb1.x; bgo1 = bb1.y;
    }

    // per-step x loader: tid<224 -> (element e, feature kx)
    const float* xp = x;
    if (tid < EPB * ISZ)
        xp = x + (size_t)(blk * EPB + (tid & 31)) * (TSTEPS * ISZ) + (tid >> 5);

    float c0[4] = {0.f, 0.f, 0.f, 0.f};
    float c1[4] = {0.f, 0.f, 0.f, 0.f};

    int buf = 0;
    for (int t = 0; t < TSTEPS; t++) {
        // prefetch x_{t+1}; lands during compute
        float xv = 0.f;
        if (tid < EPB * ISZ && t + 1 < TSTEPS) xv = xp[(t + 1) * ISZ];

        const int bo = buf * (HSZ * EPB);   // h buffer offset
        const int bn = (buf ^ 1) * (HSZ * EPB);
        const int xo = buf * (ISZ * EPB);

        // ---- layer 0 ----
        if (act) {
            u64 aif[4] = {bif0, bif0, bif0, bif0};
            u64 ago[4] = {bgo0, bgo0, bgo0, bgo0};
            mvN<HSZ>(sm + OFF_WH0, sm + OFF_H0A + bo, sm + OFF_H0B + bo, j, g4, aif, ago);
            mvN<ISZ>(sm + OFF_WX0, sm + OFF_XA + xo, sm + OFF_XB + xo, j, g4, aif, ago);
            float hn[4];
            gates4(aif, ago, c0, hn);
            *reinterpret_cast<float4*>(sm + OFF_H0A + bn + j * EPB + g4) =
                make_float4(hn[0], hn[0], hn[1], hn[1]);
            *reinterpret_cast<float4*>(sm + OFF_H0B + bn + j * EPB + g4) =
                make_float4(hn[2], hn[2], hn[3], hn[3]);
        }
        __syncthreads();   // A: new h0 visible

        // ---- layer 1 ----
        if (act) {
            u64 aif[4] = {bif1, bif1, bif1, bif1};
            u64 ago[4] = {bgo1, bgo1, bgo1, bgo1};
            mvN<HSZ>(sm + OFF_WI1, sm + OFF_H0A + bn, sm + OFF_H0B + bn, j, g4, aif, ago);
            mvN<HSZ>(sm + OFF_WH1, sm + OFF_H1A + bo, sm + OFF_H1B + bo, j, g4, aif, ago);
            float hn[4];
            gates4(aif, ago, c1, hn);
            *reinterpret_cast<float4*>(sm + OFF_H1A + bn + j * EPB + g4) =
                make_float4(hn[0], hn[0], hn[1], hn[1]);
            *reinterpret_cast<float4*>(sm + OFF_H1B + bn + j * EPB + g4) =
                make_float4(hn[2], hn[2], hn[3], hn[3]);
        }
        // store x_{t+1} duplicated into the other buffer
        if (tid < EPB * ISZ) {
            const int e = tid & 31, kx = tid >> 5;
            const int gg = e >> 2, r = e & 3;
            float* dst = sm + (r < 2 ? OFF_XA : OFF_XB) + (xo ^ (ISZ * EPB))
                         + kx * EPB + gg * 4 + (r & 1) * 2;
            *reinterpret_cast<u64*>(dst) = pk2(xv, xv);
        }
        __syncthreads();   // B: new h1 + new x visible
        buf ^= 1;
    }

    // ---- FC head: out[e][j] = b_fc[j] + sum_k w_fc[j][k] * h2[e][k] ----
    if (j < ISZ) {
        const int bo = buf * (HSZ * EPB);
        const float bv = sm[OFF_BFC + j];
        float s[4] = {bv, bv, bv, bv};
        #pragma unroll 10
        for (int k = 0; k < HSZ; k++) {
            const float wv = sm[OFF_WFC + j * HSZ + k];
            const int ra = OFF_H0A; (void)ra;
            const float h0v = sm[OFF_H1A + bo + k * EPB + g4];      // elem 4g
            const float h1v = sm[OFF_H1A + bo + k * EPB + g4 + 2];  // elem 4g+1
            const float h2v = sm[OFF_H1B + bo + k * EPB + g4];      // elem 4g+2
            const float h3v = sm[OFF_H1B + bo + k * EPB + g4 + 2];  // elem 4g+3
            s[0] = fmaf(wv, h0v, s[0]);
            s[1] = fmaf(wv, h1v, s[1]);
            s[2] = fmaf(wv, h2v, s[2]);
            s[3] = fmaf(wv, h3v, s[3]);
        }
        #pragma unroll
        for (int e = 0; e < 4; e++)
            out[(size_t)(blk * EPB + g * 4 + e) * ISZ + j] = s[e];
    }
}

extern "C" void kernel_launch(void* const* d_in, const int* in_sizes, int n_in,
                              void* d_out, int out_size)
{
    const float* x     = (const float*)d_in[0];
    const float* w_ih0 = (const float*)d_in[1];
    const float* w_hh0 = (const float*)d_in[2];
    const float* b_ih0 = (const float*)d_in[3];
    const float* b_hh0 = (const float*)d_in[4];
    const float* w_ih1 = (const float*)d_in[5];
    const float* w_hh1 = (const float*)d_in[6];
    const float* b_ih1 = (const float*)d_in[7];
    const float* b_hh1 = (const float*)d_in[8];
    const float* w_fc  = (const float*)d_in[9];
    const float* b_fc  = (const float*)d_in[10];
    float* out = (float*)d_out;

    const size_t smem_bytes = SMEM_FLOATS * sizeof(float);
    cudaFuncSetAttribute(lstm2_fused_v3,
                         cudaFuncAttributeMaxDynamicSharedMemorySize,
                         (int)smem_bytes);

    lstm2_fused_v3<<<NBLOCKS, NTHREADS, smem_bytes>>>(
        x, w_ih0, w_hh0, b_ih0, b_hh0,
        w_ih1, w_hh1, b_ih1, b_hh1,
        w_fc, b_fc, out);
}

// round 7
// speedup vs baseline: 1.5856x; 1.5856x over previous
#include <cuda_runtime.h>
#include <cstdint>

#define TSTEPS 256
#define HSZ 50
#define ISZ 7
#define EPB 32
#define NTHREADS 256
#define NBLOCKS 128

typedef unsigned long long u64;

// smem layout (float offsets)
#define OFF_WX0 0        // [7][50][4]   1400
#define OFF_WH0 1400     // [50][50][4] 10000
#define OFF_WI1 11400    // [50][50][4] 10000
#define OFF_WH1 21400    // [50][50][4] 10000
#define OFF_B0  31400    // [50][4]       200
#define OFF_B1  31600    // [50][4]       200
#define OFF_WFC 31800    // [7][50]       350
#define OFF_BFC 32152    // [8]             8
#define OFF_XS  32160    // [2][7][32]    448
#define OFF_H0  32608    // [2][50][32]  3200
#define OFF_H1  35808    // [2][50][32]  3200
#define SMEM_FLOATS 39008

__device__ __forceinline__ u64 pk2(float lo, float hi) {
    u64 r; asm("mov.b64 %0,{%1,%2};" : "=l"(r) : "f"(lo), "f"(hi)); return r;
}
__device__ __forceinline__ void upk2(float& lo, float& hi, u64 v) {
    asm("mov.b64 {%0,%1},%2;" : "=f"(lo), "=f"(hi) : "l"(v));
}
__device__ __forceinline__ void fma2(u64& c, u64 a, u64 b) {
    asm("fma.rn.f32x2 %0,%1,%2,%0;" : "+l"(c) : "l"(a), "l"(b));
}

__device__ __forceinline__ float sigm(float v) {
    return __fdividef(1.f, 1.f + __expf(-v));
}
__device__ __forceinline__ float tanh_f(float v) {
    return __fdividef(2.f, 1.f + __expf(-2.f * v)) - 1.f;
}

// 50-step matvec accumulate. Wp: packed weights [(k*50+j)*4 + gate].
// hb: h base already offset by this thread's g*8 (row stride 32 floats).
// acc[gate*4 + p], pair p covers elements 2p, 2p+1.
__device__ __forceinline__ void mv50(const float* __restrict__ Wp,
                                     const float* __restrict__ hb,
                                     int j, u64 acc[16]) {
    #pragma unroll 10
    for (int k = 0; k < HSZ; k++) {
        const float4 w4 = *reinterpret_cast<const float4*>(Wp + (k * HSZ + j) * 4);
        const u64 wi = pk2(w4.x, w4.x), wf = pk2(w4.y, w4.y);
        const u64 wg = pk2(w4.z, w4.z), wo = pk2(w4.w, w4.w);
        const ulonglong2 ha = *reinterpret_cast<const ulonglong2*>(hb + k * EPB);
        const ulonglong2 hc = *reinterpret_cast<const ulonglong2*>(hb + k * EPB + 4);
        fma2(acc[0],  wi, ha.x); fma2(acc[1],  wi, ha.y); fma2(acc[2],  wi, hc.x); fma2(acc[3],  wi, hc.y);
        fma2(acc[4],  wf, ha.x); fma2(acc[5],  wf, ha.y); fma2(acc[6],  wf, hc.x); fma2(acc[7],  wf, hc.y);
        fma2(acc[8],  wg, ha.x); fma2(acc[9],  wg, ha.y); fma2(acc[10], wg, hc.x); fma2(acc[11], wg, hc.y);
        fma2(acc[12], wo, ha.x); fma2(acc[13], wo, ha.y); fma2(acc[14], wo, hc.x); fma2(acc[15], wo, hc.y);
    }
}

// Merged dual matvec for layer 1: accumulates Wa*ha and Wb*hb in one k-loop.
// Doubles independent work per iteration so LDS latency is covered at low warp count.
__device__ __forceinline__ void mv50x2(const float* __restrict__ Wa,
                                       const float* __restrict__ Wb,
                                       const float* __restrict__ ha,
                                       const float* __restrict__ hb,
                                       int j, u64 acc[16]) {
    #pragma unroll 5
    for (int k = 0; k < HSZ; k++) {
        const float4 wa = *reinterpret_cast<const float4*>(Wa + (k * HSZ + j) * 4);
        const ulonglong2 a1 = *reinterpret_cast<const ulonglong2*>(ha + k * EPB);
        const ulonglong2 a2 = *reinterpret_cast<const ulonglong2*>(ha + k * EPB + 4);
        const float4 wb = *reinterpret_cast<const float4*>(Wb + (k * HSZ + j) * 4);
        const ulonglong2 b1 = *reinterpret_cast<const ulonglong2*>(hb + k * EPB);
        const ulonglong2 b2 = *reinterpret_cast<const ulonglong2*>(hb + k * EPB + 4);

        const u64 wia = pk2(wa.x, wa.x), wfa = pk2(wa.y, wa.y);
        const u64 wga = pk2(wa.z, wa.z), woa = pk2(wa.w, wa.w);
        const u64 wib = pk2(wb.x, wb.x), wfb = pk2(wb.y, wb.y);
        const u64 wgb = pk2(wb.z, wb.z), wob = pk2(wb.w, wb.w);

        fma2(acc[0],  wia, a1.x); fma2(acc[1],  wia, a1.y); fma2(acc[2],  wia, a2.x); fma2(acc[3],  wia, a2.y);
        fma2(acc[4],  wfa, a1.x); fma2(acc[5],  wfa, a1.y); fma2(acc[6],  wfa, a2.x); fma2(acc[7],  wfa, a2.y);
        fma2(acc[8],  wga, a1.x); fma2(acc[9],  wga, a1.y); fma2(acc[10], wga, a2.x); fma2(acc[11], wga, a2.y);
        fma2(acc[12], woa, a1.x); fma2(acc[13], woa, a1.y); fma2(acc[14], woa, a2.x); fma2(acc[15], woa, a2.y);

        fma2(acc[0],  wib, b1.x); fma2(acc[1],  wib, b1.y); fma2(acc[2],  wib, b2.x); fma2(acc[3],  wib, b2.y);
        fma2(acc[4],  wfb, b1.x); fma2(acc[5],  wfb, b1.y); fma2(acc[6],  wfb, b2.x); fma2(acc[7],  wfb, b2.y);
        fma2(acc[8],  wgb, b1.x); fma2(acc[9],  wgb, b1.y); fma2(acc[10], wgb, b2.x); fma2(acc[11], wgb, b2.y);
        fma2(acc[12], wob, b1.x); fma2(acc[13], wob, b1.y); fma2(acc[14], wob, b2.x); fma2(acc[15], wob, b2.y);
    }
}

__device__ __forceinline__ void mv7(const float* __restrict__ Wp,
                                    const float* __restrict__ xb,
                                    int j, u64 acc[16]) {
    #pragma unroll
    for (int k = 0; k < ISZ; k++) {
        const float4 w4 = *reinterpret_cast<const float4*>(Wp + (k * HSZ + j) * 4);
        const u64 wi = pk2(w4.x, w4.x), wf = pk2(w4.y, w4.y);
        const u64 wg = pk2(w4.z, w4.z), wo = pk2(w4.w, w4.w);
        const ulonglong2 ha = *reinterpret_cast<const ulonglong2*>(xb + k * EPB);
        const ulonglong2 hc = *reinterpret_cast<const ulonglong2*>(xb + k * EPB + 4);
        fma2(acc[0],  wi, ha.x); fma2(acc[1],  wi, ha.y); fma2(acc[2],  wi, hc.x); fma2(acc[3],  wi, hc.y);
        fma2(acc[4],  wf, ha.x); fma2(acc[5],  wf, ha.y); fma2(acc[6],  wf, hc.x); fma2(acc[7],  wf, hc.y);
        fma2(acc[8],  wg, ha.x); fma2(acc[9],  wg, ha.y); fma2(acc[10], wg, hc.x); fma2(acc[11], wg, hc.y);
        fma2(acc[12], wo, ha.x); fma2(acc[13], wo, ha.y); fma2(acc[14], wo, hc.x); fma2(acc[15], wo, hc.y);
    }
}

__device__ __forceinline__ void gates(const u64 acc[16], float c[8], float hn[8]) {
    #pragma unroll
    for (int p = 0; p < 4; p++) {
        float i0, i1, f0, f1, g0, g1, o0, o1;
        upk2(i0, i1, acc[p]);
        upk2(f0, f1, acc[4 + p]);
        upk2(g0, g1, acc[8 + p]);
        upk2(o0, o1, acc[12 + p]);
        const int e = 2 * p;
        c[e]     = sigm(f0) * c[e]     + sigm(i0) * tanh_f(g0);
        c[e + 1] = sigm(f1) * c[e + 1] + sigm(i1) * tanh_f(g1);
        hn[e]     = sigm(o0) * tanh_f(c[e]);
        hn[e + 1] = sigm(o1) * tanh_f(c[e + 1]);
    }
}

__global__ __launch_bounds__(NTHREADS, 1)
void lstm2_fused_v4(const float* __restrict__ x,
                    const float* __restrict__ w_ih0, const float* __restrict__ w_hh0,
                    const float* __restrict__ b_ih0, const float* __restrict__ b_hh0,
                    const float* __restrict__ w_ih1, const float* __restrict__ w_hh1,
                    const float* __restrict__ b_ih1, const float* __restrict__ b_hh1,
                    const float* __restrict__ w_fc,  const float* __restrict__ b_fc,
                    float* __restrict__ out)
{
    extern __shared__ float sm[];
    const int tid = threadIdx.x;
    const int blk = blockIdx.x;

    // ---- stage weights to shared, packed/transposed ----
    for (int i = tid; i < HSZ * HSZ * 4; i += NTHREADS) {       // 10000 each
        const int k = i / 200, r = i % 200;
        const int j = r >> 2, gi = r & 3;
        const int src = (gi * HSZ + j) * HSZ + k;
        sm[OFF_WH0 + i] = w_hh0[src];
        sm[OFF_WI1 + i] = w_ih1[src];
        sm[OFF_WH1 + i] = w_hh1[src];
    }
    for (int i = tid; i < ISZ * HSZ * 4; i += NTHREADS) {       // 1400
        const int k = i / 200, r = i % 200;
        const int j = r >> 2, gi = r & 3;
        sm[OFF_WX0 + i] = w_ih0[(gi * HSZ + j) * ISZ + k];
    }
    for (int i = tid; i < 200; i += NTHREADS) {
        const int j = i >> 2, gi = i & 3;
        sm[OFF_B0 + i] = b_ih0[gi * HSZ + j] + b_hh0[gi * HSZ + j];
        sm[OFF_B1 + i] = b_ih1[gi * HSZ + j] + b_hh1[gi * HSZ + j];
    }
    for (int i = tid; i < ISZ * HSZ; i += NTHREADS) sm[OFF_WFC + i] = w_fc[i];
    if (tid < ISZ) sm[OFF_BFC + tid] = b_fc[tid];
    // zero both h buffers
    for (int i = tid; i < 2 * HSZ * EPB; i += NTHREADS) {
        sm[OFF_H0 + i] = 0.f;
        sm[OFF_H1 + i] = 0.f;
    }
    // preload x for t=0 into xs buffer 0: xs[k][e]
    for (int i = tid; i < ISZ * EPB; i += NTHREADS) {
        const int e = i & 31, kx = i >> 5;
        sm[OFF_XS + kx * 32 + e] = x[(size_t)(blk * EPB + e) * (TSTEPS * ISZ) + kx];
    }
    __syncthreads();

    const int j = tid >> 2;          // cell 0..63 (active < 50)
    const int g = tid & 3;           // element group, 8 elems each
    const bool act = (j < HSZ);
    const int go = g * 8;            // element offset within block

    float4 b0v = make_float4(0.f, 0.f, 0.f, 0.f), b1v = b0v;
    if (act) {
        b0v = *reinterpret_cast<const float4*>(sm + OFF_B0 + j * 4);
        b1v = *reinterpret_cast<const float4*>(sm + OFF_B1 + j * 4);
    }

    // per-step x loader: tid<224, kx = tid>>5, e = tid&31
    const float* xp = x;
    if (tid < EPB * ISZ)
        xp = x + (size_t)(blk * EPB + (tid & 31)) * (TSTEPS * ISZ) + (tid >> 5);

    float c0[8] = {0.f, 0.f, 0.f, 0.f, 0.f, 0.f, 0.f, 0.f};
    float c1[8] = {0.f, 0.f, 0.f, 0.f, 0.f, 0.f, 0.f, 0.f};
    u64 acc[16];

    int buf = 0;
    for (int t = 0; t < TSTEPS; t++) {
        // prefetch x_{t+1} (lands during compute)
        float xv = 0.f;
        if (tid < EPB * ISZ && t + 1 < TSTEPS) xv = xp[(t + 1) * ISZ];

        // ---- layer 0 ----
        if (act) {
            #pragma unroll
            for (int p = 0; p < 4; p++) {
                acc[p]      = pk2(b0v.x, b0v.x);
                acc[4 + p]  = pk2(b0v.y, b0v.y);
                acc[8 + p]  = pk2(b0v.z, b0v.z);
                acc[12 + p] = pk2(b0v.w, b0v.w);
            }
            mv50(sm + OFF_WH0, sm + OFF_H0 + buf * 1600 + go, j, acc);
            mv7 (sm + OFF_WX0, sm + OFF_XS + buf * 224  + go, j, acc);
            float hn[8];
            gates(acc, c0, hn);
            float* hd = sm + OFF_H0 + (buf ^ 1) * 1600 + j * EPB + go;
            *reinterpret_cast<float4*>(hd)     = make_float4(hn[0], hn[1], hn[2], hn[3]);
            *reinterpret_cast<float4*>(hd + 4) = make_float4(hn[4], hn[5], hn[6], hn[7]);
        }
        __syncthreads();   // A: new h0 visible

        // ---- layer 1 (merged dual matvec) ----
        if (act) {
            #pragma unroll
            for (int p = 0; p < 4; p++) {
                acc[p]      = pk2(b1v.x, b1v.x);
                acc[4 + p]  = pk2(b1v.y, b1v.y);
                acc[8 + p]  = pk2(b1v.z, b1v.z);
                acc[12 + p] = pk2(b1v.w, b1v.w);
            }
            mv50x2(sm + OFF_WI1, sm + OFF_WH1,
                   sm + OFF_H0 + (buf ^ 1) * 1600 + go,
                   sm + OFF_H1 + buf * 1600 + go,
                   j, acc);
            float hn[8];
            gates(acc, c1, hn);
            float* hd = sm + OFF_H1 + (buf ^ 1) * 1600 + j * EPB + go;
            *reinterpret_cast<float4*>(hd)     = make_float4(hn[0], hn[1], hn[2], hn[3]);
            *reinterpret_cast<float4*>(hd + 4) = make_float4(hn[4], hn[5], hn[6], hn[7]);
        }
        if (tid < EPB * ISZ) sm[OFF_XS + (buf ^ 1) * 224 + tid] = xv;
        __syncthreads();   // B: new h1 + new x visible
        buf ^= 1;
    }

    // ---- FC head ----
    if (j < ISZ) {
        const float* h2 = sm + OFF_H1 + buf * 1600 + go;
        float s[8];
        const float bv = sm[OFF_BFC + j];
        #pragma unroll
        for (int e = 0; e < 8; e++) s[e] = bv;
        #pragma unroll 10
        for (int k = 0; k < HSZ; k++) {
            const float wv = sm[OFF_WFC + j * HSZ + k];
            #pragma unroll
            for (int e = 0; e < 8; e++) s[e] = fmaf(wv, h2[k * EPB + e], s[e]);
        }
        #pragma unroll
        for (int e = 0; e < 8; e++)
            out[(size_t)(blk * EPB + go + e) * ISZ + j] = s[e];
    }
}

extern "C" void kernel_launch(void* const* d_in, const int* in_sizes, int n_in,
                              void* d_out, int out_size)
{
    const float* x     = (const float*)d_in[0];
    const float* w_ih0 = (const float*)d_in[1];
    const float* w_hh0 = (const float*)d_in[2];
    const float* b_ih0 = (const float*)d_in[3];
    const float* b_hh0 = (const float*)d_in[4];
    const float* w_ih1 = (const float*)d_in[5];
    const float* w_hh1 = (const float*)d_in[6];
    const float* b_ih1 = (const float*)d_in[7];
    const float* b_hh1 = (const float*)d_in[8];
    const float* w_fc  = (const float*)d_in[9];
    const float* b_fc  = (const float*)d_in[10];
    float* out = (float*)d_out;

    const size_t smem_bytes = SMEM_FLOATS * sizeof(float);
    cudaFuncSetAttribute(lstm2_fused_v4,
                         cudaFuncAttributeMaxDynamicSharedMemorySize,
                         (int)smem_bytes);

    lstm2_fused_v4<<<NBLOCKS, NTHREADS, smem_bytes>>>(
        x, w_ih0, w_hh0, b_ih0, b_hh0,
        w_ih1, w_hh1, b_ih1, b_hh1,
        w_fc, b_fc, out);
}